// round 15
// baseline (speedup 1.0000x reference)
#include <cuda_runtime.h>
#include <cuda_bf16.h>

#define B_   4
#define S_   2048
#define H_   1024
#define NH_  16
#define DH_  64
#define M_   (B_ * S_)   // 8192

// -------------------- scratch (allocation-free) ----------------------------
__device__ __nv_bfloat16 g_xb[M_ * H_];
__device__ __nv_bfloat16 g_wq[H_ * H_];
__device__ __nv_bfloat16 g_wk[H_ * H_];
__device__ __nv_bfloat16 g_wv[H_ * H_];
__device__ __nv_bfloat16 g_wo[H_ * H_];
__device__ __nv_bfloat16 g_q[B_ * NH_ * S_ * DH_];
__device__ __nv_bfloat16 g_k[B_ * NH_ * S_ * DH_];
__device__ __nv_bfloat16 g_v[B_ * NH_ * S_ * DH_];
__device__ __nv_bfloat16 g_ctx[M_ * H_];
__device__ float         g_h[M_ * H_];

// -------------------- helpers ----------------------------------------------
__device__ __forceinline__ void mma_bf16(float c[4], const unsigned a[4],
                                         const unsigned b[2]) {
    asm volatile(
        "mma.sync.aligned.m16n8k16.row.col.f32.bf16.bf16.f32 "
        "{%0,%1,%2,%3}, {%4,%5,%6,%7}, {%8,%9}, {%0,%1,%2,%3};\n"
        : "+f"(c[0]), "+f"(c[1]), "+f"(c[2]), "+f"(c[3])
        : "r"(a[0]), "r"(a[1]), "r"(a[2]), "r"(a[3]), "r"(b[0]), "r"(b[1]));
}

__device__ __forceinline__ void ldsm_x4(unsigned r[4], unsigned addr) {
    asm volatile("ldmatrix.sync.aligned.m8n8.x4.shared.b16 {%0,%1,%2,%3}, [%4];"
                 : "=r"(r[0]), "=r"(r[1]), "=r"(r[2]), "=r"(r[3]) : "r"(addr));
}
__device__ __forceinline__ void ldsm_x4t(unsigned r[4], unsigned addr) {
    asm volatile("ldmatrix.sync.aligned.m8n8.x4.trans.shared.b16 {%0,%1,%2,%3}, [%4];"
                 : "=r"(r[0]), "=r"(r[1]), "=r"(r[2]), "=r"(r[3]) : "r"(addr));
}

__device__ __forceinline__ void cp16(unsigned dst, const void* src) {
    asm volatile("cp.async.cg.shared.global [%0], [%1], 16;\n" ::"r"(dst), "l"(src));
}
__device__ __forceinline__ void cp_commit() {
    asm volatile("cp.async.commit_group;\n");
}
template <int N> __device__ __forceinline__ void cp_wait() {
    asm volatile("cp.async.wait_group %0;\n" ::"n"(N));
}

__device__ __forceinline__ unsigned pack_bf16(float lo, float hi) {
    __nv_bfloat162 p = __float22bfloat162_rn(make_float2(lo, hi));
    return *(unsigned*)&p;
}

// -------------------- fp32 -> bf16 conversion pre-pass ----------------------
__global__ __launch_bounds__(256) void convert_bf16(
    const float* __restrict__ X,
    const float* __restrict__ Wq, const float* __restrict__ Wk,
    const float* __restrict__ Wv, const float* __restrict__ Wo)
{
    const size_t i = ((size_t)blockIdx.x * 256 + threadIdx.x) * 4;
    const float* src;
    __nv_bfloat16* dst;
    size_t off;
    if (i < (size_t)M_ * H_) {
        src = X; dst = g_xb; off = i;
    } else {
        size_t w = i - (size_t)M_ * H_;
        int which = (int)(w >> 20);
        off = w & ((1u << 20) - 1);
        if (which == 0)      { src = Wq; dst = g_wq; }
        else if (which == 1) { src = Wk; dst = g_wk; }
        else if (which == 2) { src = Wv; dst = g_wv; }
        else                 { src = Wo; dst = g_wo; }
    }
    float4 v = *(const float4*)(src + off);
    *(__nv_bfloat162*)(dst + off)     = __float22bfloat162_rn(make_float2(v.x, v.y));
    *(__nv_bfloat162*)(dst + off + 2) = __float22bfloat162_rn(make_float2(v.z, v.w));
}

// ---------------------------------------------------------------------------
// bf16 tensor-core GEMM: C[m,n] = A[m,:] . W[n,:]
// 128x128 CTA tile, 4 warps, warp tile 64x64 (mma:ldsm = 4:1).
// BK=32, 4-stage cp.async, fragments via ldmatrix.x4.
// ---------------------------------------------------------------------------
#define STR  20
#define STGW (128 * STR)
#define STG  4

__global__ __launch_bounds__(128) void gemm_bf16(
    const __nv_bfloat16* __restrict__ A,
    const __nv_bfloat16* __restrict__ W0,
    const __nv_bfloat16* __restrict__ W1,
    const __nv_bfloat16* __restrict__ W2,
    const float* __restrict__ b0p,
    const float* __restrict__ b1p,
    const float* __restrict__ b2p,
    const float* __restrict__ Xres,
    int mode)
{
    const __nv_bfloat16* W;
    const float* bias;
    __nv_bfloat16* outb = nullptr;
    if (mode == 0) {
        if (blockIdx.z == 0)      { W = W0; bias = b0p; outb = g_q; }
        else if (blockIdx.z == 1) { W = W1; bias = b1p; outb = g_k; }
        else                      { W = W2; bias = b2p; outb = g_v; }
    } else {
        W = W0; bias = b0p;
    }

    extern __shared__ unsigned smw[];
    unsigned* As = smw;
    unsigned* Bs = smw + STG * STGW;
    const unsigned sA = (unsigned)__cvta_generic_to_shared(As);
    const unsigned sB = (unsigned)__cvta_generic_to_shared(Bs);

    const int tid = threadIdx.x;
    const int lane = tid & 31;
    const int wid = tid >> 5;        // 0..3
    const int g = lane >> 2;
    const int t4 = lane & 3;
    const int warp_m = wid & 1;      // 2 x 64 rows
    const int warp_n = wid >> 1;     // 2 x 64 cols

    const int row0 = blockIdx.y * 128;
    const int col0 = blockIdx.x * 128;

    // loader: thread tid owns row tid of both A and B tiles (4 x 16B per stage)
    const __nv_bfloat16* Ag = A + (size_t)(row0 + tid) * H_;
    const __nv_bfloat16* Bg = W + (size_t)(col0 + tid) * H_;
    const unsigned dOffA = sA + (unsigned)(tid * STR) * 4;
    const unsigned dOffB = sB + (unsigned)(tid * STR) * 4;

    // ldmatrix per-lane source rows/cols
    const int aRow = warp_m * 64 + (lane & 15);                         // + mt*16
    const int aCol = (lane >> 4) << 2;                                  // + kw
    const int bRow = warp_n * 64 + ((lane >> 4) & 1) * 8 + (lane & 7);  // + ntp*16
    const int bCol = ((lane >> 3) & 1) << 2;                            // + kw

    float acc[4][8][4];
    #pragma unroll
    for (int i = 0; i < 4; i++)
        #pragma unroll
        for (int j = 0; j < 8; j++)
            #pragma unroll
            for (int c = 0; c < 4; c++) acc[i][j][c] = 0.f;

    const int NIT = H_ / 32;   // 32

    #pragma unroll
    for (int s = 0; s < STG - 1; s++) {
        const int k0 = s * 32;
        const unsigned so = (unsigned)(s * STGW) * 4;
        #pragma unroll
        for (int c = 0; c < 4; c++) {
            cp16(dOffA + so + c * 16, Ag + k0 + c * 8);
            cp16(dOffB + so + c * 16, Bg + k0 + c * 8);
        }
        cp_commit();
    }

    for (int it = 0; it < NIT; it++) {
        cp_wait<STG - 2>();
        __syncthreads();

        if (it + STG - 1 < NIT) {
            const int s = (it + STG - 1) & (STG - 1);
            const int k0 = (it + STG - 1) * 32;
            const unsigned so = (unsigned)(s * STGW) * 4;
            #pragma unroll
            for (int c = 0; c < 4; c++) {
                cp16(dOffA + so + c * 16, Ag + k0 + c * 8);
                cp16(dOffB + so + c * 16, Bg + k0 + c * 8);
            }
        }
        cp_commit();

        const unsigned asb = sA + (unsigned)((it & (STG - 1)) * STGW) * 4;
        const unsigned bsb = sB + (unsigned)((it & (STG - 1)) * STGW) * 4;
        #pragma unroll
        for (int kk = 0; kk < 2; kk++) {
            const int kw = kk * 8;
            unsigned af[4][4], bf[8][2];
            #pragma unroll
            for (int mt = 0; mt < 4; mt++)
                ldsm_x4(af[mt], asb + (unsigned)((aRow + mt * 16) * STR + kw + aCol) * 4);
            #pragma unroll
            for (int ntp = 0; ntp < 4; ntp++) {
                unsigned t[4];
                ldsm_x4(t, bsb + (unsigned)((bRow + ntp * 16) * STR + kw + bCol) * 4);
                bf[2 * ntp][0] = t[0]; bf[2 * ntp][1] = t[1];
                bf[2 * ntp + 1][0] = t[2]; bf[2 * ntp + 1][1] = t[3];
            }
            #pragma unroll
            for (int mt = 0; mt < 4; mt++)
                #pragma unroll
                for (int nt = 0; nt < 8; nt++)
                    mma_bf16(acc[mt][nt], af[mt], bf[nt]);
        }
    }

    // epilogue
    #pragma unroll
    for (int mt = 0; mt < 4; mt++) {
        const int rg = row0 + warp_m * 64 + mt * 16 + g;
        #pragma unroll
        for (int nt = 0; nt < 8; nt++) {
            const int n = col0 + warp_n * 64 + nt * 8 + 2 * t4;
            const float b0 = bias[n], b1 = bias[n + 1];
            if (mode == 0) {
                const int nh = n >> 6, d = n & 63;
                #pragma unroll
                for (int h = 0; h < 2; h++) {
                    const int m = rg + h * 8;
                    const int bb = m >> 11, s = m & 2047;
                    __nv_bfloat162 v = __float22bfloat162_rn(
                        make_float2(acc[mt][nt][2 * h] + b0,
                                    acc[mt][nt][2 * h + 1] + b1));
                    *(__nv_bfloat162*)&outb[(((size_t)bb * NH_ + nh) * S_ + s) * DH_ + d] = v;
                }
            } else {
                #pragma unroll
                for (int h = 0; h < 2; h++) {
                    const int m = rg + h * 8;
                    const size_t idx = (size_t)m * H_ + n;
                    float2 r = *(const float2*)&Xres[idx];
                    float2 v = make_float2(acc[mt][nt][2 * h] + b0 + r.x,
                                           acc[mt][nt][2 * h + 1] + b1 + r.y);
                    *(float2*)&g_h[idx] = v;
                }
            }
        }
    }
}

// ---------------------------------------------------------------------------
// Flash attention, bf16. 8 warps, 128 q-rows/block, double-buffered KV via
// cp.async, fragments via ldmatrix. (Unchanged — R10-proven.)
// ---------------------------------------------------------------------------
#define QSW 36
#define KVW (64 * QSW)   // words per KV buffer = 2304

__global__ __launch_bounds__(256) void flash_attn_bf16()
{
    extern __shared__ unsigned smu[];
    unsigned* QPw = smu;                    // 128*QSW = 4608 words
    const unsigned qpb = (unsigned)__cvta_generic_to_shared(QPw);
    const unsigned kb  = qpb + 4608u * 4;   // K buffers [2][KVW]
    const unsigned vb  = kb + 2u * KVW * 4; // V buffers [2][KVW]

    const int bh = blockIdx.y;
    const int q0 = blockIdx.x * 128;
    const __nv_bfloat16* Q = g_q + (size_t)bh * S_ * DH_;
    const __nv_bfloat16* K = g_k + (size_t)bh * S_ * DH_;
    const __nv_bfloat16* V = g_v + (size_t)bh * S_ * DH_;

    const int tid = threadIdx.x;
    const int lane = tid & 31;
    const int wid = tid >> 5;
    const int g = lane >> 2;
    const int t4 = lane & 3;
    const int qr = wid * 16;

    // cp.async chunk mapping (16B chunks; 512 per tile)
    const int c0 = tid, c1 = tid + 256;
    const unsigned kd0 = (unsigned)((c0 >> 3) * QSW + (c0 & 7) * 4) * 4;
    const unsigned kd1 = (unsigned)((c1 >> 3) * QSW + (c1 & 7) * 4) * 4;

    // prologue: issue KV tile 0 into buffer 0
    {
        const char* Kg = (const char*)K;
        const char* Vg = (const char*)V;
        cp16(kb + kd0, Kg + c0 * 16);
        cp16(kb + kd1, Kg + c1 * 16);
        cp16(vb + kd0, Vg + c0 * 16);
        cp16(vb + kd1, Vg + c1 * 16);
        cp_commit();
    }

    // load Q tile (plain loads, overlapped with the cp.async above)
    {
        const uint4* Qg = (const uint4*)(Q + (size_t)q0 * DH_);
        for (int i = tid; i < 1024; i += 256) {
            const int r = i >> 3, c = i & 7;
            *(uint4*)&QPw[r * QSW + c * 4] = Qg[i];
        }
    }
    __syncthreads();

    unsigned qa[4][4];
    #pragma unroll
    for (int kk = 0; kk < 4; kk++) {
        const int r = qr + g;
        qa[kk][0] = QPw[r * QSW + kk * 8 + t4];
        qa[kk][1] = QPw[(r + 8) * QSW + kk * 8 + t4];
        qa[kk][2] = QPw[r * QSW + kk * 8 + t4 + 4];
        qa[kk][3] = QPw[(r + 8) * QSW + kk * 8 + t4 + 4];
    }

    // ldmatrix per-lane addressing pieces
    const int kRow = ((lane >> 4) & 1) * 8 + (lane & 7);  // + ntp*16
    const int kCol = ((lane >> 3) & 1) << 2;              // + kk*8
    const int pRow = qr + (lane & 15);
    const int pCol = (lane >> 4) << 2;                    // + kk*8
    const int vRow = lane & 15;                           // + kk*16
    const int vCol = (lane >> 4) << 2;                    // + nt2*8

    float m_i[2] = {-1e30f, -1e30f};
    float l_i[2] = {0.f, 0.f};
    float oc[8][4];
    #pragma unroll
    for (int n = 0; n < 8; n++)
        #pragma unroll
        for (int c = 0; c < 4; c++) oc[n][c] = 0.f;

    const int NT = S_ / 64;   // 32
    for (int jt = 0; jt < NT; jt++) {
        // issue next tile into the other buffer
        if (jt + 1 < NT) {
            const int nb = (jt + 1) & 1;
            const char* Kg = (const char*)(K + (size_t)(jt + 1) * 64 * DH_);
            const char* Vg = (const char*)(V + (size_t)(jt + 1) * 64 * DH_);
            cp16(kb + (unsigned)(nb * KVW) * 4 + kd0, Kg + c0 * 16);
            cp16(kb + (unsigned)(nb * KVW) * 4 + kd1, Kg + c1 * 16);
            cp16(vb + (unsigned)(nb * KVW) * 4 + kd0, Vg + c0 * 16);
            cp16(vb + (unsigned)(nb * KVW) * 4 + kd1, Vg + c1 * 16);
            cp_commit();
            cp_wait<1>();
        } else {
            cp_wait<0>();
        }
        __syncthreads();

        const unsigned kbuf = kb + (unsigned)((jt & 1) * KVW) * 4;
        const unsigned vbuf = vb + (unsigned)((jt & 1) * KVW) * 4;

        // scores = Q . K^T  (16 q rows x 64 keys per warp)
        float sc[8][4];
        #pragma unroll
        for (int nt = 0; nt < 8; nt++)
            #pragma unroll
            for (int c = 0; c < 4; c++) sc[nt][c] = 0.f;
        #pragma unroll
        for (int kk = 0; kk < 4; kk++) {
            #pragma unroll
            for (int ntp = 0; ntp < 4; ntp++) {
                unsigned t[4];
                ldsm_x4(t, kbuf + (unsigned)((ntp * 16 + kRow) * QSW + kk * 8 + kCol) * 4);
                unsigned blo[2] = {t[0], t[1]};
                unsigned bhi[2] = {t[2], t[3]};
                mma_bf16(sc[2 * ntp],     qa[kk], blo);
                mma_bf16(sc[2 * ntp + 1], qa[kk], bhi);
            }
        }

        // online softmax (rows g and g+8)
        #pragma unroll
        for (int h = 0; h < 2; h++) {
            const int i0 = h * 2;
            float mx = -1e30f;
            #pragma unroll
            for (int nt = 0; nt < 8; nt++) {
                sc[nt][i0]     *= 0.125f;
                sc[nt][i0 + 1] *= 0.125f;
                mx = fmaxf(mx, fmaxf(sc[nt][i0], sc[nt][i0 + 1]));
            }
            mx = fmaxf(mx, __shfl_xor_sync(0xffffffffu, mx, 1));
            mx = fmaxf(mx, __shfl_xor_sync(0xffffffffu, mx, 2));
            const float m_new = fmaxf(m_i[h], mx);
            const float alpha = __expf(m_i[h] - m_new);
            m_i[h] = m_new;
            float rs = 0.f;
            const int prow = qr + g + h * 8;
            #pragma unroll
            for (int nt = 0; nt < 8; nt++) {
                const float p0 = __expf(sc[nt][i0] - m_new);
                const float p1 = __expf(sc[nt][i0 + 1] - m_new);
                rs += p0 + p1;
                QPw[prow * QSW + nt * 4 + t4] = pack_bf16(p0, p1);
            }
            rs += __shfl_xor_sync(0xffffffffu, rs, 1);
            rs += __shfl_xor_sync(0xffffffffu, rs, 2);
            l_i[h] = l_i[h] * alpha + rs;
            #pragma unroll
            for (int nt = 0; nt < 8; nt++) {
                oc[nt][i0]     *= alpha;
                oc[nt][i0 + 1] *= alpha;
            }
        }
        __syncwarp();

        // O += P . V
        #pragma unroll
        for (int kk = 0; kk < 4; kk++) {
            unsigned pa[4];
            ldsm_x4(pa, qpb + (unsigned)(pRow * QSW + kk * 8 + pCol) * 4);
            #pragma unroll
            for (int nt2 = 0; nt2 < 4; nt2++) {
                unsigned t[4];
                ldsm_x4t(t, vbuf + (unsigned)((kk * 16 + vRow) * QSW + nt2 * 8 + vCol) * 4);
                unsigned blo[2] = {t[0], t[1]};
                unsigned bhi[2] = {t[2], t[3]};
                mma_bf16(oc[2 * nt2],     pa, blo);
                mma_bf16(oc[2 * nt2 + 1], pa, bhi);
            }
        }
        __syncthreads();
    }

    // epilogue: ctx (bf16) in [B, S, H]
    const int bb = bh >> 4;
    const int nh = bh & 15;
    const float inv0 = 1.0f / l_i[0];
    const float inv1 = 1.0f / l_i[1];
    #pragma unroll
    for (int nt = 0; nt < 8; nt++) {
        const int d = nt * 8 + 2 * t4;
        const int s0 = q0 + qr + g;
        __nv_bfloat162 v0 = __float22bfloat162_rn(
            make_float2(oc[nt][0] * inv0, oc[nt][1] * inv0));
        __nv_bfloat162 v1 = __float22bfloat162_rn(
            make_float2(oc[nt][2] * inv1, oc[nt][3] * inv1));
        *(__nv_bfloat162*)&g_ctx[((size_t)bb * S_ + s0) * H_ + nh * DH_ + d] = v0;
        *(__nv_bfloat162*)&g_ctx[((size_t)bb * S_ + s0 + 8) * H_ + nh * DH_ + d] = v1;
    }
}

// ---------------------------------------------------------------------------
// LayerNorm
// ---------------------------------------------------------------------------
__global__ __launch_bounds__(256) void layernorm(
    const float* __restrict__ gamma, const float* __restrict__ beta,
    float* __restrict__ out)
{
    __shared__ float sh1[8];
    __shared__ float sh2[8];

    const int row = blockIdx.x;
    const int tid = threadIdx.x;
    const float4 v = ((const float4*)(g_h + (size_t)row * H_))[tid];

    float sum = v.x + v.y + v.z + v.w;
    float sq  = v.x * v.x + v.y * v.y + v.z * v.z + v.w * v.w;

    #pragma unroll
    for (int off = 16; off >= 1; off >>= 1) {
        sum += __shfl_xor_sync(0xffffffffu, sum, off);
        sq  += __shfl_xor_sync(0xffffffffu, sq,  off);
    }
    const int wid = tid >> 5;
    if ((tid & 31) == 0) { sh1[wid] = sum; sh2[wid] = sq; }
    __syncthreads();
    if (tid < 8) {
        sum = sh1[tid]; sq = sh2[tid];
        #pragma unroll
        for (int off = 4; off >= 1; off >>= 1) {
            sum += __shfl_xor_sync(0xffu, sum, off);
            sq  += __shfl_xor_sync(0xffu, sq,  off);
        }
        if (tid == 0) { sh1[0] = sum; sh2[0] = sq; }
    }
    __syncthreads();

    const float mean = sh1[0] * (1.0f / H_);
    const float var  = sh2[0] * (1.0f / H_) - mean * mean;
    const float rstd = rsqrtf(var + 1e-12f);

    const float4 gv = ((const float4*)gamma)[tid];
    const float4 bt = ((const float4*)beta)[tid];
    float4 r;
    r.x = (v.x - mean) * rstd * gv.x + bt.x;
    r.y = (v.y - mean) * rstd * gv.y + bt.y;
    r.z = (v.z - mean) * rstd * gv.z + bt.z;
    r.w = (v.w - mean) * rstd * gv.w + bt.w;
    ((float4*)(out + (size_t)row * H_))[tid] = r;
}

// ---------------------------------------------------------------------------
extern "C" void kernel_launch(void* const* d_in, const int* in_sizes, int n_in,
                              void* d_out, int out_size)
{
    const float* X     = (const float*)d_in[0];
    const float* Wq    = (const float*)d_in[1];
    const float* bq    = (const float*)d_in[2];
    const float* Wk    = (const float*)d_in[3];
    const float* bk    = (const float*)d_in[4];
    const float* Wv    = (const float*)d_in[5];
    const float* bv    = (const float*)d_in[6];
    const float* Wo    = (const float*)d_in[7];
    const float* bo    = (const float*)d_in[8];
    const float* gamma = (const float*)d_in[9];
    const float* beta  = (const float*)d_in[10];
    float* out = (float*)d_out;

    __nv_bfloat16 *xb, *wq, *wk, *wv, *wo, *ctxb;
    cudaGetSymbolAddress((void**)&xb,   g_xb);
    cudaGetSymbolAddress((void**)&wq,   g_wq);
    cudaGetSymbolAddress((void**)&wk,   g_wk);
    cudaGetSymbolAddress((void**)&wv,   g_wv);
    cudaGetSymbolAddress((void**)&wo,   g_wo);
    cudaGetSymbolAddress((void**)&ctxb, g_ctx);

    const int gemm_smem = STG * STGW * 2 * (int)sizeof(unsigned);      // 81920
    cudaFuncSetAttribute(gemm_bf16, cudaFuncAttributeMaxDynamicSharedMemorySize,
                         gemm_smem);
    const int attn_smem = (4608 + 4 * KVW) * (int)sizeof(unsigned);    // 55296
    cudaFuncSetAttribute(flash_attn_bf16,
                         cudaFuncAttributeMaxDynamicSharedMemorySize, attn_smem);

    // 0) fp32 -> bf16 conversion
    convert_bf16<<<12288, 256>>>(X, Wq, Wk, Wv, Wo);

    // 1) QKV projections
    gemm_bf16<<<dim3(H_ / 128, M_ / 128, 3), 128, gemm_smem>>>(
        xb, wq, wk, wv, bq, bk, bv, nullptr, 0);

    // 2) flash attention
    flash_attn_bf16<<<dim3(S_ / 128, B_ * NH_), 256, attn_smem>>>();

    // 3) output projection + bias + residual
    gemm_bf16<<<dim3(H_ / 128, M_ / 128, 1), 128, gemm_smem>>>(
        ctxb, wo, nullptr, nullptr, bo, nullptr, nullptr, X, 1);

    // 4) layernorm
    layernorm<<<M_, 256>>>(gamma, beta, out);
}

// round 16
// speedup vs baseline: 1.2318x; 1.2318x over previous
#include <cuda_runtime.h>
#include <cuda_bf16.h>

#define B_   4
#define S_   2048
#define H_   1024
#define NH_  16
#define DH_  64
#define M_   (B_ * S_)   // 8192

// -------------------- scratch (allocation-free) ----------------------------
__device__ __nv_bfloat16 g_xb[M_ * H_];
__device__ __nv_bfloat16 g_wq[H_ * H_];
__device__ __nv_bfloat16 g_wk[H_ * H_];
__device__ __nv_bfloat16 g_wv[H_ * H_];
__device__ __nv_bfloat16 g_wo[H_ * H_];
__device__ __nv_bfloat16 g_q[B_ * NH_ * S_ * DH_];
__device__ __nv_bfloat16 g_k[B_ * NH_ * S_ * DH_];
__device__ __nv_bfloat16 g_v[B_ * NH_ * S_ * DH_];
__device__ __nv_bfloat16 g_ctx[M_ * H_];
__device__ float         g_h[M_ * H_];

// -------------------- helpers ----------------------------------------------
__device__ __forceinline__ void mma_bf16(float c[4], const unsigned a[4],
                                         const unsigned b[2]) {
    asm volatile(
        "mma.sync.aligned.m16n8k16.row.col.f32.bf16.bf16.f32 "
        "{%0,%1,%2,%3}, {%4,%5,%6,%7}, {%8,%9}, {%0,%1,%2,%3};\n"
        : "+f"(c[0]), "+f"(c[1]), "+f"(c[2]), "+f"(c[3])
        : "r"(a[0]), "r"(a[1]), "r"(a[2]), "r"(a[3]), "r"(b[0]), "r"(b[1]));
}

__device__ __forceinline__ void ldsm_x4(unsigned r[4], unsigned addr) {
    asm volatile("ldmatrix.sync.aligned.m8n8.x4.shared.b16 {%0,%1,%2,%3}, [%4];"
                 : "=r"(r[0]), "=r"(r[1]), "=r"(r[2]), "=r"(r[3]) : "r"(addr));
}
__device__ __forceinline__ void ldsm_x4t(unsigned r[4], unsigned addr) {
    asm volatile("ldmatrix.sync.aligned.m8n8.x4.trans.shared.b16 {%0,%1,%2,%3}, [%4];"
                 : "=r"(r[0]), "=r"(r[1]), "=r"(r[2]), "=r"(r[3]) : "r"(addr));
}

__device__ __forceinline__ void cp16(unsigned dst, const void* src) {
    asm volatile("cp.async.cg.shared.global [%0], [%1], 16;\n" ::"r"(dst), "l"(src));
}
__device__ __forceinline__ void cp_commit() {
    asm volatile("cp.async.commit_group;\n");
}
template <int N> __device__ __forceinline__ void cp_wait() {
    asm volatile("cp.async.wait_group %0;\n" ::"n"(N));
}

__device__ __forceinline__ unsigned pack_bf16(float lo, float hi) {
    __nv_bfloat162 p = __float22bfloat162_rn(make_float2(lo, hi));
    return *(unsigned*)&p;
}

// -------------------- fp32 -> bf16 conversion pre-pass ----------------------
__global__ __launch_bounds__(256) void convert_bf16(
    const float* __restrict__ X,
    const float* __restrict__ Wq, const float* __restrict__ Wk,
    const float* __restrict__ Wv, const float* __restrict__ Wo)
{
    const size_t i = ((size_t)blockIdx.x * 256 + threadIdx.x) * 4;
    const float* src;
    __nv_bfloat16* dst;
    size_t off;
    if (i < (size_t)M_ * H_) {
        src = X; dst = g_xb; off = i;
    } else {
        size_t w = i - (size_t)M_ * H_;
        int which = (int)(w >> 20);
        off = w & ((1u << 20) - 1);
        if (which == 0)      { src = Wq; dst = g_wq; }
        else if (which == 1) { src = Wk; dst = g_wk; }
        else if (which == 2) { src = Wv; dst = g_wv; }
        else                 { src = Wo; dst = g_wo; }
    }
    float4 v = *(const float4*)(src + off);
    *(__nv_bfloat162*)(dst + off)     = __float22bfloat162_rn(make_float2(v.x, v.y));
    *(__nv_bfloat162*)(dst + off + 2) = __float22bfloat162_rn(make_float2(v.z, v.w));
}

// ---------------------------------------------------------------------------
// bf16 tensor-core GEMM: C[m,n] = A[m,:] . W[n,:]
// 128x128 tile, BK=32, 4-stage cp.async, fragments via ldmatrix.x4.
// 8 warps, warp tile 64x32. (R10-proven configuration.)
// ---------------------------------------------------------------------------
#define STR  20
#define STGW (128 * STR)
#define STG  4

__global__ __launch_bounds__(256, 2) void gemm_bf16(
    const __nv_bfloat16* __restrict__ A,
    const __nv_bfloat16* __restrict__ W0,
    const __nv_bfloat16* __restrict__ W1,
    const __nv_bfloat16* __restrict__ W2,
    const float* __restrict__ b0p,
    const float* __restrict__ b1p,
    const float* __restrict__ b2p,
    const float* __restrict__ Xres,
    int mode)
{
    const __nv_bfloat16* W;
    const float* bias;
    __nv_bfloat16* outb = nullptr;
    if (mode == 0) {
        if (blockIdx.z == 0)      { W = W0; bias = b0p; outb = g_q; }
        else if (blockIdx.z == 1) { W = W1; bias = b1p; outb = g_k; }
        else                      { W = W2; bias = b2p; outb = g_v; }
    } else {
        W = W0; bias = b0p;
    }

    extern __shared__ unsigned smw[];
    unsigned* As = smw;
    unsigned* Bs = smw + STG * STGW;
    const unsigned sA = (unsigned)__cvta_generic_to_shared(As);
    const unsigned sB = (unsigned)__cvta_generic_to_shared(Bs);

    const int tid = threadIdx.x;
    const int lane = tid & 31;
    const int wid = tid >> 5;
    const int g = lane >> 2;
    const int t4 = lane & 3;
    const int warp_m = wid & 1;
    const int warp_n = wid >> 1;

    const int row0 = blockIdx.y * 128;
    const int col0 = blockIdx.x * 128;

    const int ldr = tid >> 1;
    const int hh = tid & 1;

    const __nv_bfloat16* Ag = A + (size_t)(row0 + ldr) * H_ + hh * 16;
    const __nv_bfloat16* Bg = W + (size_t)(col0 + ldr) * H_ + hh * 16;
    const unsigned dOffA = sA + (unsigned)(ldr * STR + hh * 8) * 4;
    const unsigned dOffB = sB + (unsigned)(ldr * STR + hh * 8) * 4;

    // ldmatrix per-lane source rows/cols
    const int aRow = warp_m * 64 + (lane & 15);        // + mt*16
    const int aCol = (lane >> 4) << 2;                 // + kw
    const int bRow = warp_n * 32 + ((lane >> 4) & 1) * 8 + (lane & 7);  // + ntp*16
    const int bCol = ((lane >> 3) & 1) << 2;           // + kw

    float acc[4][4][4];
    #pragma unroll
    for (int i = 0; i < 4; i++)
        #pragma unroll
        for (int j = 0; j < 4; j++)
            #pragma unroll
            for (int c = 0; c < 4; c++) acc[i][j][c] = 0.f;

    const int NIT = H_ / 32;

    #pragma unroll
    for (int s = 0; s < STG - 1; s++) {
        const int k0 = s * 32;
        const unsigned so = (unsigned)(s * STGW) * 4;
        cp16(dOffA + so,      Ag + k0);
        cp16(dOffA + so + 16, Ag + k0 + 8);
        cp16(dOffB + so,      Bg + k0);
        cp16(dOffB + so + 16, Bg + k0 + 8);
        cp_commit();
    }

    for (int it = 0; it < NIT; it++) {
        cp_wait<STG - 2>();
        __syncthreads();

        if (it + STG - 1 < NIT) {
            const int s = (it + STG - 1) & (STG - 1);
            const int k0 = (it + STG - 1) * 32;
            const unsigned so = (unsigned)(s * STGW) * 4;
            cp16(dOffA + so,      Ag + k0);
            cp16(dOffA + so + 16, Ag + k0 + 8);
            cp16(dOffB + so,      Bg + k0);
            cp16(dOffB + so + 16, Bg + k0 + 8);
        }
        cp_commit();

        const unsigned asb = sA + (unsigned)((it & (STG - 1)) * STGW) * 4;
        const unsigned bsb = sB + (unsigned)((it & (STG - 1)) * STGW) * 4;
        #pragma unroll
        for (int kk = 0; kk < 2; kk++) {
            const int kw = kk * 8;
            unsigned af[4][4], bf[4][2];
            #pragma unroll
            for (int ntp = 0; ntp < 2; ntp++) {
                unsigned t[4];
                ldsm_x4(t, bsb + (unsigned)((bRow + ntp * 16) * STR + kw + bCol) * 4);
                bf[2 * ntp][0] = t[0]; bf[2 * ntp][1] = t[1];
                bf[2 * ntp + 1][0] = t[2]; bf[2 * ntp + 1][1] = t[3];
            }
            #pragma unroll
            for (int mt = 0; mt < 4; mt++)
                ldsm_x4(af[mt], asb + (unsigned)((aRow + mt * 16) * STR + kw + aCol) * 4);
            #pragma unroll
            for (int mt = 0; mt < 4; mt++)
                #pragma unroll
                for (int nt = 0; nt < 4; nt++)
                    mma_bf16(acc[mt][nt], af[mt], bf[nt]);
        }
    }

    // epilogue
    #pragma unroll
    for (int mt = 0; mt < 4; mt++) {
        const int rg = row0 + warp_m * 64 + mt * 16 + g;
        #pragma unroll
        for (int nt = 0; nt < 4; nt++) {
            const int n = col0 + warp_n * 32 + nt * 8 + 2 * t4;
            const float b0 = bias[n], b1 = bias[n + 1];
            if (mode == 0) {
                const int nh = n >> 6, d = n & 63;
                #pragma unroll
                for (int h = 0; h < 2; h++) {
                    const int m = rg + h * 8;
                    const int bb = m >> 11, s = m & 2047;
                    __nv_bfloat162 v = __float22bfloat162_rn(
                        make_float2(acc[mt][nt][2 * h] + b0,
                                    acc[mt][nt][2 * h + 1] + b1));
                    *(__nv_bfloat162*)&outb[(((size_t)bb * NH_ + nh) * S_ + s) * DH_ + d] = v;
                }
            } else {
                #pragma unroll
                for (int h = 0; h < 2; h++) {
                    const int m = rg + h * 8;
                    const size_t idx = (size_t)m * H_ + n;
                    float2 r = *(const float2*)&Xres[idx];
                    float2 v = make_float2(acc[mt][nt][2 * h] + b0 + r.x,
                                           acc[mt][nt][2 * h + 1] + b1 + r.y);
                    *(float2*)&g_h[idx] = v;
                }
            }
        }
    }
}

// ---------------------------------------------------------------------------
// Flash attention, bf16. 8 warps, 128 q-rows/block, TRIPLE-buffered KV via
// cp.async (one barrier per tile), fragments via ldmatrix.
// ---------------------------------------------------------------------------
#define QSW 36
#define KVW (64 * QSW)   // words per KV buffer = 2304

__global__ __launch_bounds__(256) void flash_attn_bf16()
{
    extern __shared__ unsigned smu[];
    unsigned* QPw = smu;                    // 128*QSW = 4608 words
    const unsigned qpb = (unsigned)__cvta_generic_to_shared(QPw);
    const unsigned kb  = qpb + 4608u * 4;   // K buffers [3][KVW]
    const unsigned vb  = kb + 3u * KVW * 4; // V buffers [3][KVW]

    const int bh = blockIdx.y;
    const int q0 = blockIdx.x * 128;
    const __nv_bfloat16* Q = g_q + (size_t)bh * S_ * DH_;
    const __nv_bfloat16* K = g_k + (size_t)bh * S_ * DH_;
    const __nv_bfloat16* V = g_v + (size_t)bh * S_ * DH_;

    const int tid = threadIdx.x;
    const int lane = tid & 31;
    const int wid = tid >> 5;
    const int g = lane >> 2;
    const int t4 = lane & 3;
    const int qr = wid * 16;

    // cp.async chunk mapping (16B chunks; 512 per tile)
    const int c0 = tid, c1 = tid + 256;
    const unsigned kd0 = (unsigned)((c0 >> 3) * QSW + (c0 & 7) * 4) * 4;
    const unsigned kd1 = (unsigned)((c1 >> 3) * QSW + (c1 & 7) * 4) * 4;

    // prologue: issue KV tile 0 into buffer 0
    {
        const char* Kg = (const char*)K;
        const char* Vg = (const char*)V;
        cp16(kb + kd0, Kg + c0 * 16);
        cp16(kb + kd1, Kg + c1 * 16);
        cp16(vb + kd0, Vg + c0 * 16);
        cp16(vb + kd1, Vg + c1 * 16);
        cp_commit();
    }

    // load Q tile (plain loads, overlapped with the cp.async above)
    {
        const uint4* Qg = (const uint4*)(Q + (size_t)q0 * DH_);
        for (int i = tid; i < 1024; i += 256) {
            const int r = i >> 3, c = i & 7;
            *(uint4*)&QPw[r * QSW + c * 4] = Qg[i];
        }
    }
    __syncthreads();

    unsigned qa[4][4];
    #pragma unroll
    for (int kk = 0; kk < 4; kk++) {
        const int r = qr + g;
        qa[kk][0] = QPw[r * QSW + kk * 8 + t4];
        qa[kk][1] = QPw[(r + 8) * QSW + kk * 8 + t4];
        qa[kk][2] = QPw[r * QSW + kk * 8 + t4 + 4];
        qa[kk][3] = QPw[(r + 8) * QSW + kk * 8 + t4 + 4];
    }

    // ldmatrix per-lane addressing pieces
    const int kRow = ((lane >> 4) & 1) * 8 + (lane & 7);  // + ntp*16
    const int kCol = ((lane >> 3) & 1) << 2;              // + kk*8
    const int pRow = qr + (lane & 15);
    const int pCol = (lane >> 4) << 2;                    // + kk*8
    const int vRow = lane & 15;                           // + kk*16
    const int vCol = (lane >> 4) << 2;                    // + nt2*8

    float m_i[2] = {-1e30f, -1e30f};
    float l_i[2] = {0.f, 0.f};
    float oc[8][4];
    #pragma unroll
    for (int n = 0; n < 8; n++)
        #pragma unroll
        for (int c = 0; c < 4; c++) oc[n][c] = 0.f;

    const int NT = S_ / 64;   // 32
    int cur = 0;              // rotating buffer index (jt % 3)
    for (int jt = 0; jt < NT; jt++) {
        // issue next tile into buffer (cur+1)%3; safe vs laggards reading
        // buffer (cur+2)%3 (their tile jt-1): all three distinct.
        if (jt + 1 < NT) {
            const int nb = (cur == 2) ? 0 : cur + 1;
            const char* Kg = (const char*)(K + (size_t)(jt + 1) * 64 * DH_);
            const char* Vg = (const char*)(V + (size_t)(jt + 1) * 64 * DH_);
            cp16(kb + (unsigned)(nb * KVW) * 4 + kd0, Kg + c0 * 16);
            cp16(kb + (unsigned)(nb * KVW) * 4 + kd1, Kg + c1 * 16);
            cp16(vb + (unsigned)(nb * KVW) * 4 + kd0, Vg + c0 * 16);
            cp16(vb + (unsigned)(nb * KVW) * 4 + kd1, Vg + c1 * 16);
            cp_commit();
            cp_wait<1>();
        } else {
            cp_wait<0>();
        }
        __syncthreads();   // visibility of buffer `cur` across threads

        const unsigned kbuf = kb + (unsigned)(cur * KVW) * 4;
        const unsigned vbuf = vb + (unsigned)(cur * KVW) * 4;

        // scores = Q . K^T  (16 q rows x 64 keys per warp)
        float sc[8][4];
        #pragma unroll
        for (int nt = 0; nt < 8; nt++)
            #pragma unroll
            for (int c = 0; c < 4; c++) sc[nt][c] = 0.f;
        #pragma unroll
        for (int kk = 0; kk < 4; kk++) {
            #pragma unroll
            for (int ntp = 0; ntp < 4; ntp++) {
                unsigned t[4];
                ldsm_x4(t, kbuf + (unsigned)((ntp * 16 + kRow) * QSW + kk * 8 + kCol) * 4);
                unsigned blo[2] = {t[0], t[1]};
                unsigned bhi[2] = {t[2], t[3]};
                mma_bf16(sc[2 * ntp],     qa[kk], blo);
                mma_bf16(sc[2 * ntp + 1], qa[kk], bhi);
            }
        }

        // online softmax (rows g and g+8)
        #pragma unroll
        for (int h = 0; h < 2; h++) {
            const int i0 = h * 2;
            float mx = -1e30f;
            #pragma unroll
            for (int nt = 0; nt < 8; nt++) {
                sc[nt][i0]     *= 0.125f;
                sc[nt][i0 + 1] *= 0.125f;
                mx = fmaxf(mx, fmaxf(sc[nt][i0], sc[nt][i0 + 1]));
            }
            mx = fmaxf(mx, __shfl_xor_sync(0xffffffffu, mx, 1));
            mx = fmaxf(mx, __shfl_xor_sync(0xffffffffu, mx, 2));
            const float m_new = fmaxf(m_i[h], mx);
            const float alpha = __expf(m_i[h] - m_new);
            m_i[h] = m_new;
            float rs = 0.f;
            const int prow = qr + g + h * 8;
            #pragma unroll
            for (int nt = 0; nt < 8; nt++) {
                const float p0 = __expf(sc[nt][i0] - m_new);
                const float p1 = __expf(sc[nt][i0 + 1] - m_new);
                rs += p0 + p1;
                QPw[prow * QSW + nt * 4 + t4] = pack_bf16(p0, p1);
            }
            rs += __shfl_xor_sync(0xffffffffu, rs, 1);
            rs += __shfl_xor_sync(0xffffffffu, rs, 2);
            l_i[h] = l_i[h] * alpha + rs;
            #pragma unroll
            for (int nt = 0; nt < 8; nt++) {
                oc[nt][i0]     *= alpha;
                oc[nt][i0 + 1] *= alpha;
            }
        }
        __syncwarp();

        // O += P . V   (P rows are this warp's own; syncwarp suffices)
        #pragma unroll
        for (int kk = 0; kk < 4; kk++) {
            unsigned pa[4];
            ldsm_x4(pa, qpb + (unsigned)(pRow * QSW + kk * 8 + pCol) * 4);
            #pragma unroll
            for (int nt2 = 0; nt2 < 4; nt2++) {
                unsigned t[4];
                ldsm_x4t(t, vbuf + (unsigned)((kk * 16 + vRow) * QSW + nt2 * 8 + vCol) * 4);
                unsigned blo[2] = {t[0], t[1]};
                unsigned bhi[2] = {t[2], t[3]};
                mma_bf16(oc[2 * nt2],     pa, blo);
                mma_bf16(oc[2 * nt2 + 1], pa, bhi);
            }
        }
        // no end-of-tile barrier: 3-deep buffering makes the next prefetch
        // target distinct from any buffer still being read.
        cur = (cur == 2) ? 0 : cur + 1;
    }

    // epilogue: ctx (bf16) in [B, S, H]
    const int bb = bh >> 4;
    const int nh = bh & 15;
    const float inv0 = 1.0f / l_i[0];
    const float inv1 = 1.0f / l_i[1];
    #pragma unroll
    for (int nt = 0; nt < 8; nt++) {
        const int d = nt * 8 + 2 * t4;
        const int s0 = q0 + qr + g;
        __nv_bfloat162 v0 = __float22bfloat162_rn(
            make_float2(oc[nt][0] * inv0, oc[nt][1] * inv0));
        __nv_bfloat162 v1 = __float22bfloat162_rn(
            make_float2(oc[nt][2] * inv1, oc[nt][3] * inv1));
        *(__nv_bfloat162*)&g_ctx[((size_t)bb * S_ + s0) * H_ + nh * DH_ + d] = v0;
        *(__nv_bfloat162*)&g_ctx[((size_t)bb * S_ + s0 + 8) * H_ + nh * DH_ + d] = v1;
    }
}

// ---------------------------------------------------------------------------
// LayerNorm
// ---------------------------------------------------------------------------
__global__ __launch_bounds__(256) void layernorm(
    const float* __restrict__ gamma, const float* __restrict__ beta,
    float* __restrict__ out)
{
    __shared__ float sh1[8];
    __shared__ float sh2[8];

    const int row = blockIdx.x;
    const int tid = threadIdx.x;
    const float4 v = ((const float4*)(g_h + (size_t)row * H_))[tid];

    float sum = v.x + v.y + v.z + v.w;
    float sq  = v.x * v.x + v.y * v.y + v.z * v.z + v.w * v.w;

    #pragma unroll
    for (int off = 16; off >= 1; off >>= 1) {
        sum += __shfl_xor_sync(0xffffffffu, sum, off);
        sq  += __shfl_xor_sync(0xffffffffu, sq,  off);
    }
    const int wid = tid >> 5;
    if ((tid & 31) == 0) { sh1[wid] = sum; sh2[wid] = sq; }
    __syncthreads();
    if (tid < 8) {
        sum = sh1[tid]; sq = sh2[tid];
        #pragma unroll
        for (int off = 4; off >= 1; off >>= 1) {
            sum += __shfl_xor_sync(0xffu, sum, off);
            sq  += __shfl_xor_sync(0xffu, sq,  off);
        }
        if (tid == 0) { sh1[0] = sum; sh2[0] = sq; }
    }
    __syncthreads();

    const float mean = sh1[0] * (1.0f / H_);
    const float var  = sh2[0] * (1.0f / H_) - mean * mean;
    const float rstd = rsqrtf(var + 1e-12f);

    const float4 gv = ((const float4*)gamma)[tid];
    const float4 bt = ((const float4*)beta)[tid];
    float4 r;
    r.x = (v.x - mean) * rstd * gv.x + bt.x;
    r.y = (v.y - mean) * rstd * gv.y + bt.y;
    r.z = (v.z - mean) * rstd * gv.z + bt.z;
    r.w = (v.w - mean) * rstd * gv.w + bt.w;
    ((float4*)(out + (size_t)row * H_))[tid] = r;
}

// ---------------------------------------------------------------------------
extern "C" void kernel_launch(void* const* d_in, const int* in_sizes, int n_in,
                              void* d_out, int out_size)
{
    const float* X     = (const float*)d_in[0];
    const float* Wq    = (const float*)d_in[1];
    const float* bq    = (const float*)d_in[2];
    const float* Wk    = (const float*)d_in[3];
    const float* bk    = (const float*)d_in[4];
    const float* Wv    = (const float*)d_in[5];
    const float* bv    = (const float*)d_in[6];
    const float* Wo    = (const float*)d_in[7];
    const float* bo    = (const float*)d_in[8];
    const float* gamma = (const float*)d_in[9];
    const float* beta  = (const float*)d_in[10];
    float* out = (float*)d_out;

    __nv_bfloat16 *xb, *wq, *wk, *wv, *wo, *ctxb;
    cudaGetSymbolAddress((void**)&xb,   g_xb);
    cudaGetSymbolAddress((void**)&wq,   g_wq);
    cudaGetSymbolAddress((void**)&wk,   g_wk);
    cudaGetSymbolAddress((void**)&wv,   g_wv);
    cudaGetSymbolAddress((void**)&wo,   g_wo);
    cudaGetSymbolAddress((void**)&ctxb, g_ctx);

    const int gemm_smem = STG * STGW * 2 * (int)sizeof(unsigned);      // 81920
    cudaFuncSetAttribute(gemm_bf16, cudaFuncAttributeMaxDynamicSharedMemorySize,
                         gemm_smem);
    const int attn_smem = (4608 + 6 * KVW) * (int)sizeof(unsigned);    // 73728
    cudaFuncSetAttribute(flash_attn_bf16,
                         cudaFuncAttributeMaxDynamicSharedMemorySize, attn_smem);

    // 0) fp32 -> bf16 conversion
    convert_bf16<<<12288, 256>>>(X, Wq, Wk, Wv, Wo);

    // 1) QKV projections
    gemm_bf16<<<dim3(H_ / 128, M_ / 128, 3), 256, gemm_smem>>>(
        xb, wq, wk, wv, bq, bk, bv, nullptr, 0);

    // 2) flash attention
    flash_attn_bf16<<<dim3(S_ / 128, B_ * NH_), 256, attn_smem>>>();

    // 3) output projection + bias + residual
    gemm_bf16<<<dim3(H_ / 128, M_ / 128, 1), 256, gemm_smem>>>(
        ctxb, wo, nullptr, nullptr, bo, nullptr, nullptr, X, 1);

    // 4) layernorm
    layernorm<<<M_, 256>>>(gamma, beta, out);
}